// round 1
// baseline (speedup 1.0000x reference)
#include <cuda_runtime.h>
#include <math.h>

#define S 2048
#define D 2048
#define H 16
#define HD 128
#define SS_STRIDE 68

// ---- scratch (allocation-free rule: __device__ globals) ----
__device__ float g_q[H * S * HD];   // [H][S][HD]
__device__ float g_k[H * S * HD];
__device__ float g_v[H * S * HD];
__device__ float g_o[S * D];        // [S][D]

// ============================================================
// GEMM: C = A @ B^T.  A:[M,K] rm, B:[N,K] rm.
// headmode=1: C[((n>>7)*M + m)*128 + (n&127)]  (per-head layout)
// headmode=0: C[m*N + n]
// ============================================================
__global__ __launch_bounds__(256) void gemm_nt_kernel(
    const float* __restrict__ A, const float* __restrict__ B,
    float* __restrict__ C, int M, int N, int K, int headmode)
{
    __shared__ float As[8][128];
    __shared__ float Bs[8][128];
    const int t = threadIdx.x;
    const int tx = t & 15, ty = t >> 4;
    const int m0 = blockIdx.y * 128, n0 = blockIdx.x * 128;
    const int lrow = t >> 1, lk4 = (t & 1) * 4;
    const float* Ap = A + (size_t)(m0 + lrow) * K + lk4;
    const float* Bp = B + (size_t)(n0 + lrow) * K + lk4;

    float acc[8][8];
#pragma unroll
    for (int i = 0; i < 8; i++)
#pragma unroll
        for (int j = 0; j < 8; j++) acc[i][j] = 0.f;

    for (int k0 = 0; k0 < K; k0 += 8) {
        float4 av = *(const float4*)(Ap + k0);
        float4 bv = *(const float4*)(Bp + k0);
        __syncthreads();
        As[lk4 + 0][lrow] = av.x; As[lk4 + 1][lrow] = av.y;
        As[lk4 + 2][lrow] = av.z; As[lk4 + 3][lrow] = av.w;
        Bs[lk4 + 0][lrow] = bv.x; Bs[lk4 + 1][lrow] = bv.y;
        Bs[lk4 + 2][lrow] = bv.z; Bs[lk4 + 3][lrow] = bv.w;
        __syncthreads();
#pragma unroll
        for (int kk = 0; kk < 8; kk++) {
            float a[8], b[8];
            *(float4*)(a)     = *(const float4*)&As[kk][ty * 4];
            *(float4*)(a + 4) = *(const float4*)&As[kk][64 + ty * 4];
            *(float4*)(b)     = *(const float4*)&Bs[kk][tx * 4];
            *(float4*)(b + 4) = *(const float4*)&Bs[kk][64 + tx * 4];
#pragma unroll
            for (int i = 0; i < 8; i++)
#pragma unroll
                for (int j = 0; j < 8; j++)
                    acc[i][j] = fmaf(a[i], b[j], acc[i][j]);
        }
    }

#pragma unroll
    for (int i = 0; i < 8; i++) {
        int m = m0 + ((i < 4) ? (ty * 4 + i) : (64 + ty * 4 + (i - 4)));
#pragma unroll
        for (int jh = 0; jh < 2; jh++) {
            int ncol = n0 + ((jh == 0) ? (tx * 4) : (64 + tx * 4));
            float4 v = make_float4(acc[i][jh * 4 + 0], acc[i][jh * 4 + 1],
                                   acc[i][jh * 4 + 2], acc[i][jh * 4 + 3]);
            if (headmode) {
                int hh = ncol >> 7, hd = ncol & 127;
                *(float4*)&C[((size_t)hh * M + m) * 128 + hd] = v;
            } else {
                *(float4*)&C[(size_t)m * N + ncol] = v;
            }
        }
    }
}

// ============================================================
// RoPE on Q,K + IA3 (q *= l_k, v *= l_v). One block per (s,h).
// ============================================================
__global__ __launch_bounds__(128) void rope_ia3_kernel(
    float* __restrict__ Qm, float* __restrict__ Km, float* __restrict__ Vm,
    const float* __restrict__ cosT, const float* __restrict__ sinT,
    const float* __restrict__ lk, const float* __restrict__ lv)
{
    int s = blockIdx.x;
    int h = blockIdx.y;
    int d = threadIdx.x;
    size_t rowbase = ((size_t)h * S + s) * HD;
    float c  = cosT[s * HD + d];
    float sn = sinT[s * HD + d];
    int   p  = d ^ 64;
    float sign = (d < 64) ? -1.f : 1.f;
    float qd = Qm[rowbase + d], qp = Qm[rowbase + p];
    float kd = Km[rowbase + d], kp = Km[rowbase + p];
    float vd = Vm[rowbase + d];
    __syncthreads();   // all reads done before any writes
    Qm[rowbase + d] = (qd * c + sign * qp * sn) * lk[h * HD + d];
    Km[rowbase + d] = kd * c + sign * kp * sn;
    Vm[rowbase + d] = vd * lv[h * HD + d];
}

// ============================================================
// Causal flash attention, fp32, BQ=BK=64.
// Qt/Kt stored d-major [128][64], float4-quad XOR swizzle.
// Scores in Sst transposed [k][q], stride 68.
// V natural [64][128] (shares buffer with Kt).
// ============================================================
__global__ __launch_bounds__(256) void flash_kernel(
    const float* __restrict__ Q, const float* __restrict__ K,
    const float* __restrict__ V, float* __restrict__ O)
{
    extern __shared__ float sm[];
    float* Qt   = sm;                       // 128*64
    float* KVb  = Qt + 128 * 64;            // 128*64 (Kt) / 64*128 (V)
    float* Sst  = KVb + 128 * 64;           // 64*SS_STRIDE
    float* rowm = Sst + 64 * SS_STRIDE;
    float* rowl = rowm + 64;
    float* rowa = rowl + 64;

    const int t  = threadIdx.x;
    const int qt = blockIdx.x;
    const int h  = blockIdx.y;
    const float scale = 0.08838834764831845f;   // 1/sqrt(128)

    const float* Qh = Q + (size_t)h * S * HD;
    const float* Kh = K + (size_t)h * S * HD;
    const float* Vh = V + (size_t)h * S * HD;

    // load Q tile transposed + swizzled, pre-scaled
#pragma unroll
    for (int r = 0; r < 8; r++) {
        int idx = t + 256 * r;
        int row = idx >> 5;         // q row 0..63
        int c4  = idx & 31;         // d-quad 0..31
        float4 v = *(const float4*)(Qh + ((size_t)(qt * 64 + row)) * HD + c4 * 4);
        int base = 4 * ((row >> 2) ^ (c4 & 15)) + (row & 3);
        Qt[(4 * c4 + 0) * 64 + base] = v.x * scale;
        Qt[(4 * c4 + 1) * 64 + base] = v.y * scale;
        Qt[(4 * c4 + 2) * 64 + base] = v.z * scale;
        Qt[(4 * c4 + 3) * 64 + base] = v.w * scale;
    }
    if (t < 64) { rowm[t] = -1e30f; rowl[t] = 0.f; }

    float acc[4][8];
#pragma unroll
    for (int i = 0; i < 4; i++)
#pragma unroll
        for (int j = 0; j < 8; j++) acc[i][j] = 0.f;

    const int sty = t >> 4;        // score q-group (rows sty*4+i)
    const int stx = t & 15;        // score k-group (cols stx*4+j)
    const int rq  = (t & 15) * 4;  // PV q rows
    const int cd  = (t >> 4) * 8;  // PV d cols

    for (int kt = 0; kt <= qt; kt++) {
        __syncthreads();           // prev PV done with KVb/Sst; Qt ready
        // ---- load K tile transposed + swizzled ----
#pragma unroll
        for (int r = 0; r < 8; r++) {
            int idx = t + 256 * r;
            int row = idx >> 5;
            int c4  = idx & 31;
            float4 v = *(const float4*)(Kh + ((size_t)(kt * 64 + row)) * HD + c4 * 4);
            int base = 4 * ((row >> 2) ^ (c4 & 15)) + (row & 3);
            KVb[(4 * c4 + 0) * 64 + base] = v.x;
            KVb[(4 * c4 + 1) * 64 + base] = v.y;
            KVb[(4 * c4 + 2) * 64 + base] = v.z;
            KVb[(4 * c4 + 3) * 64 + base] = v.w;
        }
        __syncthreads();
        // ---- scores: 4q x 4k per thread, outer product over d ----
        float s4[4][4];
#pragma unroll
        for (int i = 0; i < 4; i++)
#pragma unroll
            for (int j = 0; j < 4; j++) s4[i][j] = 0.f;
#pragma unroll 8
        for (int dd = 0; dd < 128; dd++) {
            int sw = (dd >> 2) & 15;
            float4 qv = *(const float4*)&Qt[dd * 64 + 4 * (sty ^ sw)];
            float4 kv = *(const float4*)&KVb[dd * 64 + 4 * (stx ^ sw)];
            float qa[4] = {qv.x, qv.y, qv.z, qv.w};
            float kb[4] = {kv.x, kv.y, kv.z, kv.w};
#pragma unroll
            for (int i = 0; i < 4; i++)
#pragma unroll
                for (int j = 0; j < 4; j++)
                    s4[i][j] = fmaf(qa[i], kb[j], s4[i][j]);
        }
        // ---- causal mask + store scores transposed [k][q] ----
#pragma unroll
        for (int j = 0; j < 4; j++) {
            int kcol = kt * 64 + stx * 4 + j;
            float4 sv;
            sv.x = (kcol <= qt * 64 + sty * 4 + 0) ? s4[0][j] : -1e30f;
            sv.y = (kcol <= qt * 64 + sty * 4 + 1) ? s4[1][j] : -1e30f;
            sv.z = (kcol <= qt * 64 + sty * 4 + 2) ? s4[2][j] : -1e30f;
            sv.w = (kcol <= qt * 64 + sty * 4 + 3) ? s4[3][j] : -1e30f;
            *(float4*)&Sst[(stx * 4 + j) * SS_STRIDE + sty * 4] = sv;
        }
        __syncthreads();
        // ---- online softmax: 4 threads per q row ----
        {
            int row = t >> 2, ln = t & 3;
            float vals[16];
            float mx = -1e30f;
#pragma unroll
            for (int j = 0; j < 16; j++) {
                vals[j] = Sst[(ln + 4 * j) * SS_STRIDE + row];
                mx = fmaxf(mx, vals[j]);
            }
            mx = fmaxf(mx, __shfl_xor_sync(0xffffffffu, mx, 1));
            mx = fmaxf(mx, __shfl_xor_sync(0xffffffffu, mx, 2));
            float mold = rowm[row];
            float mnew = fmaxf(mold, mx);
            float ssum = 0.f;
#pragma unroll
            for (int j = 0; j < 16; j++) {
                float p = __expf(vals[j] - mnew);
                Sst[(ln + 4 * j) * SS_STRIDE + row] = p;
                ssum += p;
            }
            ssum += __shfl_xor_sync(0xffffffffu, ssum, 1);
            ssum += __shfl_xor_sync(0xffffffffu, ssum, 2);
            if (ln == 0) {
                float alpha = __expf(mold - mnew);
                rowa[row] = alpha;
                rowl[row] = rowl[row] * alpha + ssum;
                rowm[row] = mnew;
            }
        }
        __syncthreads();
        // ---- load V (natural layout) + rescale acc ----
#pragma unroll
        for (int r = 0; r < 8; r++) {
            int idx  = t + 256 * r;
            int row2 = idx >> 5;
            int c4   = idx & 31;
            *(float4*)&KVb[row2 * 128 + c4 * 4] =
                *(const float4*)(Vh + ((size_t)(kt * 64 + row2)) * HD + c4 * 4);
        }
#pragma unroll
        for (int i = 0; i < 4; i++) {
            float a = rowa[rq + i];
#pragma unroll
            for (int j = 0; j < 8; j++) acc[i][j] *= a;
        }
        __syncthreads();
        // ---- PV: acc[q][d] += P[q][k] * V[k][d] ----
        for (int k = 0; k < 64; k++) {
            float4 p4 = *(const float4*)&Sst[k * SS_STRIDE + rq];
            float4 v0 = *(const float4*)&KVb[k * 128 + cd];
            float4 v1 = *(const float4*)&KVb[k * 128 + cd + 4];
            float pa[4] = {p4.x, p4.y, p4.z, p4.w};
            float vv[8] = {v0.x, v0.y, v0.z, v0.w, v1.x, v1.y, v1.z, v1.w};
#pragma unroll
            for (int i = 0; i < 4; i++)
#pragma unroll
                for (int j = 0; j < 8; j++)
                    acc[i][j] = fmaf(pa[i], vv[j], acc[i][j]);
        }
    }

    // ---- epilogue: normalize and write O[s][h*128+d] ----
#pragma unroll
    for (int i = 0; i < 4; i++) {
        float inv = 1.f / rowl[rq + i];
        int q = qt * 64 + rq + i;
        float* op = O + (size_t)q * D + h * HD + cd;
        float4 o0 = make_float4(acc[i][0] * inv, acc[i][1] * inv,
                                acc[i][2] * inv, acc[i][3] * inv);
        float4 o1 = make_float4(acc[i][4] * inv, acc[i][5] * inv,
                                acc[i][6] * inv, acc[i][7] * inv);
        *(float4*)op       = o0;
        *(float4*)(op + 4) = o1;
    }
}

// ============================================================
extern "C" void kernel_launch(void* const* d_in, const int* in_sizes, int n_in,
                              void* d_out, int out_size)
{
    const float* hs   = (const float*)d_in[0];
    // d_in[1] = attention_mask (exactly causal -1e9; implemented analytically)
    const float* cosT = (const float*)d_in[2];
    const float* sinT = (const float*)d_in[3];
    const float* Wq   = (const float*)d_in[4];
    const float* Wk   = (const float*)d_in[5];
    const float* Wv   = (const float*)d_in[6];
    const float* Wo   = (const float*)d_in[7];
    const float* lk   = (const float*)d_in[8];
    const float* lv   = (const float*)d_in[9];
    float* out = (float*)d_out;
    (void)in_sizes; (void)n_in; (void)out_size;

    float *q, *k, *v, *o;
    cudaGetSymbolAddress((void**)&q, g_q);
    cudaGetSymbolAddress((void**)&k, g_k);
    cudaGetSymbolAddress((void**)&v, g_v);
    cudaGetSymbolAddress((void**)&o, g_o);

    dim3 gg(D / 128, S / 128);
    gemm_nt_kernel<<<gg, 256>>>(hs, Wq, q, S, D, D, 1);
    gemm_nt_kernel<<<gg, 256>>>(hs, Wk, k, S, D, D, 1);
    gemm_nt_kernel<<<gg, 256>>>(hs, Wv, v, S, D, D, 1);

    rope_ia3_kernel<<<dim3(S, H), 128>>>(q, k, v, cosT, sinT, lk, lv);

    int smem = (128 * 64 + 128 * 64 + 64 * SS_STRIDE + 192) * (int)sizeof(float);
    cudaFuncSetAttribute(flash_kernel,
                         cudaFuncAttributeMaxDynamicSharedMemorySize, smem);
    flash_kernel<<<dim3(S / 64, H), 256, smem>>>(q, k, v, o);

    gemm_nt_kernel<<<gg, 256>>>(o, Wo, out, S, D, D, 0);
}

// round 4
// speedup vs baseline: 1.7275x; 1.7275x over previous
#include <cuda_runtime.h>
#include <cuda_bf16.h>
#include <cstdint>
#include <math.h>

#define S 2048
#define D 2048
#define H 16
#define HD 128
#define SS_STRIDE 68

// ---- scratch (allocation-free rule: __device__ globals) ----
__device__ float g_q[H * S * HD];
__device__ float g_k[H * S * HD];
__device__ float g_v[H * S * HD];
__device__ float g_o[S * D];
__device__ __nv_bfloat16 g_hs_hi[S * D], g_hs_lo[S * D];
__device__ __nv_bfloat16 g_w_hi[4][D * D], g_w_lo[4][D * D];
__device__ __nv_bfloat16 g_o_hi[S * D], g_o_lo[S * D];

// ============================================================
// helpers (arch-agnostic: mma.sync / ldmatrix / cp.async)
// ============================================================
__device__ __forceinline__ uint32_t smem_u32(const void* p) {
    uint32_t a;
    asm("{ .reg .u64 t; cvta.to.shared.u64 t, %1; cvt.u32.u64 %0, t; }"
        : "=r"(a) : "l"(p));
    return a;
}
__device__ __forceinline__ void mma16816(float* c, const uint32_t* a,
                                         const uint32_t* b) {
    asm volatile(
        "mma.sync.aligned.m16n8k16.row.col.f32.bf16.bf16.f32 "
        "{%0,%1,%2,%3}, {%4,%5,%6,%7}, {%8,%9}, {%0,%1,%2,%3};"
        : "+f"(c[0]), "+f"(c[1]), "+f"(c[2]), "+f"(c[3])
        : "r"(a[0]), "r"(a[1]), "r"(a[2]), "r"(a[3]), "r"(b[0]), "r"(b[1]));
}
__device__ __forceinline__ void ldsm4(uint32_t* r, uint32_t addr) {
    asm volatile("ldmatrix.sync.aligned.m8n8.x4.shared.b16 {%0,%1,%2,%3}, [%4];"
                 : "=r"(r[0]), "=r"(r[1]), "=r"(r[2]), "=r"(r[3]) : "r"(addr));
}
#define CPASYNC16(sa, ga) \
    asm volatile("cp.async.cg.shared.global [%0], [%1], 16;" \
                 :: "r"(sa), "l"(ga) : "memory")
#define CP_COMMIT() asm volatile("cp.async.commit_group;" ::: "memory")
#define CP_WAIT(N)  asm volatile("cp.async.wait_group %0;" :: "n"(N) : "memory")

// ============================================================
// fp32 -> (hi, lo) bf16 split
// ============================================================
__global__ __launch_bounds__(256) void split_kernel(
    const float* __restrict__ x, __nv_bfloat16* __restrict__ hi,
    __nv_bfloat16* __restrict__ lo, int n)
{
    int i = (blockIdx.x * 256 + threadIdx.x) * 4;
    if (i >= n) return;
    float4 v = *(const float4*)(x + i);
    float f[4] = {v.x, v.y, v.z, v.w};
    __nv_bfloat16 hb[4], lb[4];
#pragma unroll
    for (int j = 0; j < 4; j++) {
        hb[j] = __float2bfloat16(f[j]);
        lb[j] = __float2bfloat16(f[j] - __bfloat162float(hb[j]));
    }
    ((__nv_bfloat162*)(hi + i))[0] = __nv_bfloat162(hb[0], hb[1]);
    ((__nv_bfloat162*)(hi + i))[1] = __nv_bfloat162(hb[2], hb[3]);
    ((__nv_bfloat162*)(lo + i))[0] = __nv_bfloat162(lb[0], lb[1]);
    ((__nv_bfloat162*)(lo + i))[1] = __nv_bfloat162(lb[2], lb[3]);
}

// ============================================================
// mma.sync split-bf16 GEMM: C = A @ B^T, M=N=K=2048.
// CTA tile 128x128, K-stage 32, cp.async double-buffered.
// Smem row pitch 80B -> ldmatrix conflict-free without swizzle.
// headmode=1: C[((n>>7)*2048 + m)*128 + (n&127)], else C[m*2048+n].
// ============================================================
#define PITCH 80
#define MATSZ (128 * PITCH)      // 10240 bytes per matrix tile
#define STAGESZ (4 * MATSZ)      // Ahi, Alo, Bhi, Blo
#define GSMEM (2 * STAGESZ)      // 81920

__global__ __launch_bounds__(256, 1) void gemm_mma_kernel(
    const __nv_bfloat16* __restrict__ Ahi, const __nv_bfloat16* __restrict__ Alo,
    const __nv_bfloat16* __restrict__ Bhi, const __nv_bfloat16* __restrict__ Blo,
    float* __restrict__ C, int headmode)
{
    extern __shared__ char smem[];
    const uint32_t sb = smem_u32(smem);
    const int t = threadIdx.x;
    const int lane = t & 31;
    const int w = t >> 5;
    const int mw = (w >> 1) * 32;      // warp m-offset in CTA tile
    const int nw = (w & 1) * 64;       // warp n-offset
    const int mbase = blockIdx.y * 128;
    const int nbase = blockIdx.x * 128;

    const __nv_bfloat16* pA_hi = Ahi + (size_t)mbase * 2048;
    const __nv_bfloat16* pA_lo = Alo + (size_t)mbase * 2048;
    const __nv_bfloat16* pB_hi = Bhi + (size_t)nbase * 2048;
    const __nv_bfloat16* pB_lo = Blo + (size_t)nbase * 2048;

    float acc[2][8][4];
#pragma unroll
    for (int i = 0; i < 2; i++)
#pragma unroll
        for (int j = 0; j < 8; j++)
#pragma unroll
            for (int k = 0; k < 4; k++) acc[i][j][k] = 0.f;

    // ---- stage loader: 128 rows x 32 bf16 (64B) per matrix, pitch 80 ----
#define LOAD_STAGE(sidx, k0) do {                                            \
        uint32_t base = sb + ((sidx) & 1) * STAGESZ;                         \
        _Pragma("unroll")                                                    \
        for (int r = 0; r < 8; r++) {                                        \
            const int mat = r >> 1;                                          \
            int rem = t + 256 * (r & 1);                                     \
            int row = rem >> 2, c = rem & 3;                                 \
            const __nv_bfloat16* g =                                         \
                (mat == 0 ? pA_hi : mat == 1 ? pA_lo : mat == 2 ? pB_hi : pB_lo) \
                + (size_t)row * 2048 + (k0) + c * 8;                         \
            CPASYNC16(base + mat * MATSZ + row * PITCH + c * 16, g);         \
        }                                                                    \
        CP_COMMIT();                                                         \
    } while (0)

    LOAD_STAGE(0, 0);

    for (int s = 0; s < 64; s++) {
        if (s < 63) { LOAD_STAGE(s + 1, (s + 1) * 32); CP_WAIT(1); }
        else        { CP_WAIT(0); }
        __syncthreads();
        const uint32_t base = sb + (s & 1) * STAGESZ;
        const uint32_t aHiB = base;
        const uint32_t aLoB = base + MATSZ;
        const uint32_t bHiB = base + 2 * MATSZ;
        const uint32_t bLoB = base + 3 * MATSZ;
#pragma unroll
        for (int ks = 0; ks < 2; ks++) {
            uint32_t a_hi[2][4], a_lo[2][4], b_hi[8][2], b_lo[8][2];
#pragma unroll
            for (int mt = 0; mt < 2; mt++) {
                int row = mw + mt * 16 + (lane & 15);
                int chunk = 2 * ks + (lane >> 4);
                uint32_t off = row * PITCH + chunk * 16;
                ldsm4(a_hi[mt], aHiB + off);
                ldsm4(a_lo[mt], aLoB + off);
            }
#pragma unroll
            for (int j = 0; j < 4; j++) {
                int row = nw + j * 16 + ((lane >> 4) << 3) + (lane & 7);
                int chunk = 2 * ks + ((lane >> 3) & 1);
                uint32_t off = row * PITCH + chunk * 16;
                uint32_t rh[4], rl[4];
                ldsm4(rh, bHiB + off);
                ldsm4(rl, bLoB + off);
                b_hi[2 * j][0] = rh[0]; b_hi[2 * j][1] = rh[1];
                b_hi[2 * j + 1][0] = rh[2]; b_hi[2 * j + 1][1] = rh[3];
                b_lo[2 * j][0] = rl[0]; b_lo[2 * j][1] = rl[1];
                b_lo[2 * j + 1][0] = rl[2]; b_lo[2 * j + 1][1] = rl[3];
            }
#pragma unroll
            for (int mt = 0; mt < 2; mt++)
#pragma unroll
                for (int nt = 0; nt < 8; nt++) {
                    mma16816(acc[mt][nt], a_hi[mt], b_hi[nt]);
                    mma16816(acc[mt][nt], a_hi[mt], b_lo[nt]);
                    mma16816(acc[mt][nt], a_lo[mt], b_hi[nt]);
                }
        }
        __syncthreads();
    }

    // ---- epilogue ----
#pragma unroll
    for (int mt = 0; mt < 2; mt++)
#pragma unroll
        for (int nt = 0; nt < 8; nt++) {
            const float* a = acc[mt][nt];
            int r0 = mbase + mw + mt * 16 + (lane >> 2);
            int n  = nbase + nw + nt * 8 + 2 * (lane & 3);
            if (headmode) {
                float* p0 = C + ((size_t)(n >> 7) * 2048 + r0) * 128 + (n & 127);
                float* p1 = C + ((size_t)(n >> 7) * 2048 + r0 + 8) * 128 + (n & 127);
                *(float2*)p0 = make_float2(a[0], a[1]);
                *(float2*)p1 = make_float2(a[2], a[3]);
            } else {
                *(float2*)(C + (size_t)r0 * 2048 + n)       = make_float2(a[0], a[1]);
                *(float2*)(C + (size_t)(r0 + 8) * 2048 + n) = make_float2(a[2], a[3]);
            }
        }
}

// ============================================================
// RoPE on Q,K + IA3 (q *= l_k, v *= l_v). One block per (s,h).
// ============================================================
__global__ __launch_bounds__(128) void rope_ia3_kernel(
    float* __restrict__ Qm, float* __restrict__ Km, float* __restrict__ Vm,
    const float* __restrict__ cosT, const float* __restrict__ sinT,
    const float* __restrict__ lk, const float* __restrict__ lv)
{
    int s = blockIdx.x;
    int h = blockIdx.y;
    int d = threadIdx.x;
    size_t rowbase = ((size_t)h * S + s) * HD;
    float c  = cosT[s * HD + d];
    float sn = sinT[s * HD + d];
    int   p  = d ^ 64;
    float sign = (d < 64) ? -1.f : 1.f;
    float qd = Qm[rowbase + d], qp = Qm[rowbase + p];
    float kd = Km[rowbase + d], kp = Km[rowbase + p];
    float vd = Vm[rowbase + d];
    __syncthreads();
    Qm[rowbase + d] = (qd * c + sign * qp * sn) * lk[h * HD + d];
    Km[rowbase + d] = kd * c + sign * kp * sn;
    Vm[rowbase + d] = vd * lv[h * HD + d];
}

// ============================================================
// Causal flash attention, fp32, BQ=BK=64.
// ============================================================
__global__ __launch_bounds__(256) void flash_kernel(
    const float* __restrict__ Q, const float* __restrict__ K,
    const float* __restrict__ V, float* __restrict__ O)
{
    extern __shared__ float sm[];
    float* Qt   = sm;
    float* KVb  = Qt + 128 * 64;
    float* Sst  = KVb + 128 * 64;
    float* rowm = Sst + 64 * SS_STRIDE;
    float* rowl = rowm + 64;
    float* rowa = rowl + 64;

    const int t  = threadIdx.x;
    const int qt = blockIdx.x;
    const int h  = blockIdx.y;
    const float scale = 0.08838834764831845f;

    const float* Qh = Q + (size_t)h * S * HD;
    const float* Kh = K + (size_t)h * S * HD;
    const float* Vh = V + (size_t)h * S * HD;

#pragma unroll
    for (int r = 0; r < 8; r++) {
        int idx = t + 256 * r;
        int row = idx >> 5;
        int c4  = idx & 31;
        float4 v = *(const float4*)(Qh + ((size_t)(qt * 64 + row)) * HD + c4 * 4);
        int base = 4 * ((row >> 2) ^ (c4 & 15)) + (row & 3);
        Qt[(4 * c4 + 0) * 64 + base] = v.x * scale;
        Qt[(4 * c4 + 1) * 64 + base] = v.y * scale;
        Qt[(4 * c4 + 2) * 64 + base] = v.z * scale;
        Qt[(4 * c4 + 3) * 64 + base] = v.w * scale;
    }
    if (t < 64) { rowm[t] = -1e30f; rowl[t] = 0.f; }

    float acc[4][8];
#pragma unroll
    for (int i = 0; i < 4; i++)
#pragma unroll
        for (int j = 0; j < 8; j++) acc[i][j] = 0.f;

    const int sty = t >> 4;
    const int stx = t & 15;
    const int rq  = (t & 15) * 4;
    const int cd  = (t >> 4) * 8;

    for (int kt = 0; kt <= qt; kt++) {
        __syncthreads();
#pragma unroll
        for (int r = 0; r < 8; r++) {
            int idx = t + 256 * r;
            int row = idx >> 5;
            int c4  = idx & 31;
            float4 v = *(const float4*)(Kh + ((size_t)(kt * 64 + row)) * HD + c4 * 4);
            int base = 4 * ((row >> 2) ^ (c4 & 15)) + (row & 3);
            KVb[(4 * c4 + 0) * 64 + base] = v.x;
            KVb[(4 * c4 + 1) * 64 + base] = v.y;
            KVb[(4 * c4 + 2) * 64 + base] = v.z;
            KVb[(4 * c4 + 3) * 64 + base] = v.w;
        }
        __syncthreads();
        float s4[4][4];
#pragma unroll
        for (int i = 0; i < 4; i++)
#pragma unroll
            for (int j = 0; j < 4; j++) s4[i][j] = 0.f;
#pragma unroll 8
        for (int dd = 0; dd < 128; dd++) {
            int sw = (dd >> 2) & 15;
            float4 qv = *(const float4*)&Qt[dd * 64 + 4 * (sty ^ sw)];
            float4 kv = *(const float4*)&KVb[dd * 64 + 4 * (stx ^ sw)];
            float qa[4] = {qv.x, qv.y, qv.z, qv.w};
            float kb[4] = {kv.x, kv.y, kv.z, kv.w};
#pragma unroll
            for (int i = 0; i < 4; i++)
#pragma unroll
                for (int j = 0; j < 4; j++)
                    s4[i][j] = fmaf(qa[i], kb[j], s4[i][j]);
        }
#pragma unroll
        for (int j = 0; j < 4; j++) {
            int kcol = kt * 64 + stx * 4 + j;
            float4 sv;
            sv.x = (kcol <= qt * 64 + sty * 4 + 0) ? s4[0][j] : -1e30f;
            sv.y = (kcol <= qt * 64 + sty * 4 + 1) ? s4[1][j] : -1e30f;
            sv.z = (kcol <= qt * 64 + sty * 4 + 2) ? s4[2][j] : -1e30f;
            sv.w = (kcol <= qt * 64 + sty * 4 + 3) ? s4[3][j] : -1e30f;
            *(float4*)&Sst[(stx * 4 + j) * SS_STRIDE + sty * 4] = sv;
        }
        __syncthreads();
        {
            int row = t >> 2, ln = t & 3;
            float vals[16];
            float mx = -1e30f;
#pragma unroll
            for (int j = 0; j < 16; j++) {
                vals[j] = Sst[(ln + 4 * j) * SS_STRIDE + row];
                mx = fmaxf(mx, vals[j]);
            }
            mx = fmaxf(mx, __shfl_xor_sync(0xffffffffu, mx, 1));
            mx = fmaxf(mx, __shfl_xor_sync(0xffffffffu, mx, 2));
            float mold = rowm[row];
            float mnew = fmaxf(mold, mx);
            float ssum = 0.f;
#pragma unroll
            for (int j = 0; j < 16; j++) {
                float p = __expf(vals[j] - mnew);
                Sst[(ln + 4 * j) * SS_STRIDE + row] = p;
                ssum += p;
            }
            ssum += __shfl_xor_sync(0xffffffffu, ssum, 1);
            ssum += __shfl_xor_sync(0xffffffffu, ssum, 2);
            if (ln == 0) {
                float alpha = __expf(mold - mnew);
                rowa[row] = alpha;
                rowl[row] = rowl[row] * alpha + ssum;
                rowm[row] = mnew;
            }
        }
        __syncthreads();
#pragma unroll
        for (int r = 0; r < 8; r++) {
            int idx  = t + 256 * r;
            int row2 = idx >> 5;
            int c4   = idx & 31;
            *(float4*)&KVb[row2 * 128 + c4 * 4] =
                *(const float4*)(Vh + ((size_t)(kt * 64 + row2)) * HD + c4 * 4);
        }
#pragma unroll
        for (int i = 0; i < 4; i++) {
            float a = rowa[rq + i];
#pragma unroll
            for (int j = 0; j < 8; j++) acc[i][j] *= a;
        }
        __syncthreads();
        for (int k = 0; k < 64; k++) {
            float4 p4 = *(const float4*)&Sst[k * SS_STRIDE + rq];
            float4 v0 = *(const float4*)&KVb[k * 128 + cd];
            float4 v1 = *(const float4*)&KVb[k * 128 + cd + 4];
            float pa[4] = {p4.x, p4.y, p4.z, p4.w};
            float vv[8] = {v0.x, v0.y, v0.z, v0.w, v1.x, v1.y, v1.z, v1.w};
#pragma unroll
            for (int i = 0; i < 4; i++)
#pragma unroll
                for (int j = 0; j < 8; j++)
                    acc[i][j] = fmaf(pa[i], vv[j], acc[i][j]);
        }
    }

#pragma unroll
    for (int i = 0; i < 4; i++) {
        float inv = 1.f / rowl[rq + i];
        int q = qt * 64 + rq + i;
        float* op = O + (size_t)q * D + h * HD + cd;
        float4 o0 = make_float4(acc[i][0] * inv, acc[i][1] * inv,
                                acc[i][2] * inv, acc[i][3] * inv);
        float4 o1 = make_float4(acc[i][4] * inv, acc[i][5] * inv,
                                acc[i][6] * inv, acc[i][7] * inv);
        *(float4*)op       = o0;
        *(float4*)(op + 4) = o1;
    }
}

// ============================================================
extern "C" void kernel_launch(void* const* d_in, const int* in_sizes, int n_in,
                              void* d_out, int out_size)
{
    const float* hs   = (const float*)d_in[0];
    const float* cosT = (const float*)d_in[2];
    const float* sinT = (const float*)d_in[3];
    const float* Wq   = (const float*)d_in[4];
    const float* Wk   = (const float*)d_in[5];
    const float* Wv   = (const float*)d_in[6];
    const float* Wo   = (const float*)d_in[7];
    const float* lk   = (const float*)d_in[8];
    const float* lv   = (const float*)d_in[9];
    float* out = (float*)d_out;
    (void)in_sizes; (void)n_in; (void)out_size;

    float *q, *k, *v, *o;
    cudaGetSymbolAddress((void**)&q, g_q);
    cudaGetSymbolAddress((void**)&k, g_k);
    cudaGetSymbolAddress((void**)&v, g_v);
    cudaGetSymbolAddress((void**)&o, g_o);
    __nv_bfloat16 *hsH, *hsL, *wH, *wL, *oH, *oL;
    cudaGetSymbolAddress((void**)&hsH, g_hs_hi);
    cudaGetSymbolAddress((void**)&hsL, g_hs_lo);
    cudaGetSymbolAddress((void**)&wH, g_w_hi);
    cudaGetSymbolAddress((void**)&wL, g_w_lo);
    cudaGetSymbolAddress((void**)&oH, g_o_hi);
    cudaGetSymbolAddress((void**)&oL, g_o_lo);

    const int n = S * D;
    const int sg = n / 4 / 256;
    split_kernel<<<sg, 256>>>(hs, hsH, hsL, n);
    split_kernel<<<sg, 256>>>(Wq, wH + 0 * (size_t)n, wL + 0 * (size_t)n, n);
    split_kernel<<<sg, 256>>>(Wk, wH + 1 * (size_t)n, wL + 1 * (size_t)n, n);
    split_kernel<<<sg, 256>>>(Wv, wH + 2 * (size_t)n, wL + 2 * (size_t)n, n);
    split_kernel<<<sg, 256>>>(Wo, wH + 3 * (size_t)n, wL + 3 * (size_t)n, n);

    cudaFuncSetAttribute(gemm_mma_kernel,
                         cudaFuncAttributeMaxDynamicSharedMemorySize, GSMEM);
    dim3 gg(D / 128, S / 128);
    gemm_mma_kernel<<<gg, 256, GSMEM>>>(hsH, hsL, wH + 0 * (size_t)n, wL + 0 * (size_t)n, q, 1);
    gemm_mma_kernel<<<gg, 256, GSMEM>>>(hsH, hsL, wH + 1 * (size_t)n, wL + 1 * (size_t)n, k, 1);
    gemm_mma_kernel<<<gg, 256, GSMEM>>>(hsH, hsL, wH + 2 * (size_t)n, wL + 2 * (size_t)n, v, 1);

    rope_ia3_kernel<<<dim3(S, H), 128>>>(q, k, v, cosT, sinT, lk, lv);

    int smem = (128 * 64 + 128 * 64 + 64 * SS_STRIDE + 192) * (int)sizeof(float);
    cudaFuncSetAttribute(flash_kernel,
                         cudaFuncAttributeMaxDynamicSharedMemorySize, smem);
    flash_kernel<<<dim3(S / 64, H), 256, smem>>>(q, k, v, o);

    split_kernel<<<sg, 256>>>(o, oH, oL, n);
    gemm_mma_kernel<<<gg, 256, GSMEM>>>(oH, oL, wH + 3 * (size_t)n, wL + 3 * (size_t)n, out, 0);
}

// round 5
// speedup vs baseline: 2.7488x; 1.5912x over previous
#include <cuda_runtime.h>
#include <cuda_bf16.h>
#include <cstdint>
#include <math.h>

#define S 2048
#define D 2048
#define H 16
#define HD 128

// ---- scratch (allocation-free rule: __device__ globals) ----
__device__ float g_q[H * S * HD];
__device__ float g_k[H * S * HD];
__device__ float g_v[H * S * HD];
__device__ float g_o[S * D];
__device__ __nv_bfloat16 g_hs_hi[S * D], g_hs_lo[S * D];
__device__ __nv_bfloat16 g_w_hi[4][D * D], g_w_lo[4][D * D];
__device__ __nv_bfloat16 g_o_hi[S * D], g_o_lo[S * D];
__device__ __nv_bfloat16 g_qh[H * S * HD], g_ql[H * S * HD];
__device__ __nv_bfloat16 g_kh[H * S * HD], g_kl[H * S * HD];
__device__ __nv_bfloat16 g_vh[H * S * HD], g_vl[H * S * HD];

// ============================================================
// helpers (arch-agnostic: mma.sync / ldmatrix / cp.async)
// ============================================================
__device__ __forceinline__ uint32_t smem_u32(const void* p) {
    uint32_t a;
    asm("{ .reg .u64 t; cvta.to.shared.u64 t, %1; cvt.u32.u64 %0, t; }"
        : "=r"(a) : "l"(p));
    return a;
}
__device__ __forceinline__ void mma16816(float* c, const uint32_t* a,
                                         const uint32_t* b) {
    asm volatile(
        "mma.sync.aligned.m16n8k16.row.col.f32.bf16.bf16.f32 "
        "{%0,%1,%2,%3}, {%4,%5,%6,%7}, {%8,%9}, {%0,%1,%2,%3};"
        : "+f"(c[0]), "+f"(c[1]), "+f"(c[2]), "+f"(c[3])
        : "r"(a[0]), "r"(a[1]), "r"(a[2]), "r"(a[3]), "r"(b[0]), "r"(b[1]));
}
__device__ __forceinline__ void ldsm4(uint32_t* r, uint32_t addr) {
    asm volatile("ldmatrix.sync.aligned.m8n8.x4.shared.b16 {%0,%1,%2,%3}, [%4];"
                 : "=r"(r[0]), "=r"(r[1]), "=r"(r[2]), "=r"(r[3]) : "r"(addr));
}
__device__ __forceinline__ void ldsm4t(uint32_t* r, uint32_t addr) {
    asm volatile("ldmatrix.sync.aligned.m8n8.x4.trans.shared.b16 {%0,%1,%2,%3}, [%4];"
                 : "=r"(r[0]), "=r"(r[1]), "=r"(r[2]), "=r"(r[3]) : "r"(addr));
}
#define CPASYNC16(sa, ga) \
    asm volatile("cp.async.cg.shared.global [%0], [%1], 16;" \
                 :: "r"(sa), "l"(ga) : "memory")
#define CP_COMMIT() asm volatile("cp.async.commit_group;" ::: "memory")
#define CP_WAIT(N)  asm volatile("cp.async.wait_group %0;" :: "n"(N) : "memory")

__device__ __forceinline__ uint32_t pk2(float a, float b) {
    __nv_bfloat162 t = __floats2bfloat162_rn(a, b);
    return *(uint32_t*)&t;
}

// ============================================================
// fp32 -> (hi, lo) bf16 split
// ============================================================
__global__ __launch_bounds__(256) void split_kernel(
    const float* __restrict__ x, __nv_bfloat16* __restrict__ hi,
    __nv_bfloat16* __restrict__ lo, int n)
{
    int i = (blockIdx.x * 256 + threadIdx.x) * 4;
    if (i >= n) return;
    float4 v = *(const float4*)(x + i);
    float f[4] = {v.x, v.y, v.z, v.w};
    __nv_bfloat16 hb[4], lb[4];
#pragma unroll
    for (int j = 0; j < 4; j++) {
        hb[j] = __float2bfloat16(f[j]);
        lb[j] = __float2bfloat16(f[j] - __bfloat162float(hb[j]));
    }
    ((__nv_bfloat162*)(hi + i))[0] = __nv_bfloat162(hb[0], hb[1]);
    ((__nv_bfloat162*)(hi + i))[1] = __nv_bfloat162(hb[2], hb[3]);
    ((__nv_bfloat162*)(lo + i))[0] = __nv_bfloat162(lb[0], lb[1]);
    ((__nv_bfloat162*)(lo + i))[1] = __nv_bfloat162(lb[2], lb[3]);
}

// ============================================================
// mma.sync split-bf16 GEMM: C = A @ B^T, M=N=K=2048. (R4, unchanged)
// ============================================================
#define PITCH 80
#define MATSZ (128 * PITCH)
#define STAGESZ (4 * MATSZ)
#define GSMEM (2 * STAGESZ)

__global__ __launch_bounds__(256, 1) void gemm_mma_kernel(
    const __nv_bfloat16* __restrict__ Ahi, const __nv_bfloat16* __restrict__ Alo,
    const __nv_bfloat16* __restrict__ Bhi, const __nv_bfloat16* __restrict__ Blo,
    float* __restrict__ C, int headmode)
{
    extern __shared__ char smem[];
    const uint32_t sb = smem_u32(smem);
    const int t = threadIdx.x;
    const int lane = t & 31;
    const int w = t >> 5;
    const int mw = (w >> 1) * 32;
    const int nw = (w & 1) * 64;
    const int mbase = blockIdx.y * 128;
    const int nbase = blockIdx.x * 128;

    const __nv_bfloat16* pA_hi = Ahi + (size_t)mbase * 2048;
    const __nv_bfloat16* pA_lo = Alo + (size_t)mbase * 2048;
    const __nv_bfloat16* pB_hi = Bhi + (size_t)nbase * 2048;
    const __nv_bfloat16* pB_lo = Blo + (size_t)nbase * 2048;

    float acc[2][8][4];
#pragma unroll
    for (int i = 0; i < 2; i++)
#pragma unroll
        for (int j = 0; j < 8; j++)
#pragma unroll
            for (int k = 0; k < 4; k++) acc[i][j][k] = 0.f;

#define LOAD_STAGE(sidx, k0) do {                                            \
        uint32_t base = sb + ((sidx) & 1) * STAGESZ;                         \
        _Pragma("unroll")                                                    \
        for (int r = 0; r < 8; r++) {                                        \
            const int mat = r >> 1;                                          \
            int rem = t + 256 * (r & 1);                                     \
            int row = rem >> 2, c = rem & 3;                                 \
            const __nv_bfloat16* g =                                         \
                (mat == 0 ? pA_hi : mat == 1 ? pA_lo : mat == 2 ? pB_hi : pB_lo) \
                + (size_t)row * 2048 + (k0) + c * 8;                         \
            CPASYNC16(base + mat * MATSZ + row * PITCH + c * 16, g);         \
        }                                                                    \
        CP_COMMIT();                                                         \
    } while (0)

    LOAD_STAGE(0, 0);

    for (int s = 0; s < 64; s++) {
        if (s < 63) { LOAD_STAGE(s + 1, (s + 1) * 32); CP_WAIT(1); }
        else        { CP_WAIT(0); }
        __syncthreads();
        const uint32_t base = sb + (s & 1) * STAGESZ;
        const uint32_t aHiB = base;
        const uint32_t aLoB = base + MATSZ;
        const uint32_t bHiB = base + 2 * MATSZ;
        const uint32_t bLoB = base + 3 * MATSZ;
#pragma unroll
        for (int ks = 0; ks < 2; ks++) {
            uint32_t a_hi[2][4], a_lo[2][4], b_hi[8][2], b_lo[8][2];
#pragma unroll
            for (int mt = 0; mt < 2; mt++) {
                int row = mw + mt * 16 + (lane & 15);
                int chunk = 2 * ks + (lane >> 4);
                uint32_t off = row * PITCH + chunk * 16;
                ldsm4(a_hi[mt], aHiB + off);
                ldsm4(a_lo[mt], aLoB + off);
            }
#pragma unroll
            for (int j = 0; j < 4; j++) {
                int row = nw + j * 16 + ((lane >> 4) << 3) + (lane & 7);
                int chunk = 2 * ks + ((lane >> 3) & 1);
                uint32_t off = row * PITCH + chunk * 16;
                uint32_t rh[4], rl[4];
                ldsm4(rh, bHiB + off);
                ldsm4(rl, bLoB + off);
                b_hi[2 * j][0] = rh[0]; b_hi[2 * j][1] = rh[1];
                b_hi[2 * j + 1][0] = rh[2]; b_hi[2 * j + 1][1] = rh[3];
                b_lo[2 * j][0] = rl[0]; b_lo[2 * j][1] = rl[1];
                b_lo[2 * j + 1][0] = rl[2]; b_lo[2 * j + 1][1] = rl[3];
            }
#pragma unroll
            for (int mt = 0; mt < 2; mt++)
#pragma unroll
                for (int nt = 0; nt < 8; nt++) {
                    mma16816(acc[mt][nt], a_hi[mt], b_hi[nt]);
                    mma16816(acc[mt][nt], a_hi[mt], b_lo[nt]);
                    mma16816(acc[mt][nt], a_lo[mt], b_hi[nt]);
                }
        }
        __syncthreads();
    }

#pragma unroll
    for (int mt = 0; mt < 2; mt++)
#pragma unroll
        for (int nt = 0; nt < 8; nt++) {
            const float* a = acc[mt][nt];
            int r0 = mbase + mw + mt * 16 + (lane >> 2);
            int n  = nbase + nw + nt * 8 + 2 * (lane & 3);
            if (headmode) {
                float* p0 = C + ((size_t)(n >> 7) * 2048 + r0) * 128 + (n & 127);
                float* p1 = C + ((size_t)(n >> 7) * 2048 + r0 + 8) * 128 + (n & 127);
                *(float2*)p0 = make_float2(a[0], a[1]);
                *(float2*)p1 = make_float2(a[2], a[3]);
            } else {
                *(float2*)(C + (size_t)r0 * 2048 + n)       = make_float2(a[0], a[1]);
                *(float2*)(C + (size_t)(r0 + 8) * 2048 + n) = make_float2(a[2], a[3]);
            }
        }
}

// ============================================================
// RoPE + IA3 + scale, emitting split bf16 q,k,v.
// q_out = (rope(q) * l_k) / sqrt(HD);  k_out = rope(k);  v_out = v * l_v
// ============================================================
__global__ __launch_bounds__(128) void rope_split_kernel(
    const float* __restrict__ Qm, const float* __restrict__ Km,
    const float* __restrict__ Vm,
    const float* __restrict__ cosT, const float* __restrict__ sinT,
    const float* __restrict__ lk, const float* __restrict__ lv,
    __nv_bfloat16* __restrict__ qh, __nv_bfloat16* __restrict__ ql,
    __nv_bfloat16* __restrict__ kh, __nv_bfloat16* __restrict__ kl,
    __nv_bfloat16* __restrict__ vh, __nv_bfloat16* __restrict__ vl)
{
    const int s = blockIdx.x;
    const int h = blockIdx.y;
    const int d = threadIdx.x;
    const float scale = 0.08838834764831845f;   // 1/sqrt(128)
    size_t rb = ((size_t)h * S + s) * HD;
    float c  = cosT[s * HD + d];
    float sn = sinT[s * HD + d];
    int   p  = d ^ 64;
    float sign = (d < 64) ? -1.f : 1.f;
    float q = (Qm[rb + d] * c + sign * Qm[rb + p] * sn) * lk[h * HD + d] * scale;
    float k = Km[rb + d] * c + sign * Km[rb + p] * sn;
    float v = Vm[rb + d] * lv[h * HD + d];
    __nv_bfloat16 qH = __float2bfloat16(q);
    __nv_bfloat16 kH = __float2bfloat16(k);
    __nv_bfloat16 vH = __float2bfloat16(v);
    qh[rb + d] = qH; ql[rb + d] = __float2bfloat16(q - __bfloat162float(qH));
    kh[rb + d] = kH; kl[rb + d] = __float2bfloat16(k - __bfloat162float(kH));
    vh[rb + d] = vH; vl[rb + d] = __float2bfloat16(v - __bfloat162float(vH));
}

// ============================================================
// Causal flash attention, mma.sync split-bf16.
// BQ=128, BK=64, 8 warps (16 q-rows each), double-buffered K/V.
// Smem rows: 128 bf16 + 8 pad = 272B pitch (conflict-free ldmatrix).
// ============================================================
#define FPB 272                 // bytes per smem row
#define QMAT (128 * FPB)        // 34816
#define KVMAT (64 * FPB)        // 17408

__global__ __launch_bounds__(256, 1) void flash_mma_kernel(
    const __nv_bfloat16* __restrict__ Qh_, const __nv_bfloat16* __restrict__ Ql_,
    const __nv_bfloat16* __restrict__ Kh_, const __nv_bfloat16* __restrict__ Kl_,
    const __nv_bfloat16* __restrict__ Vh_, const __nv_bfloat16* __restrict__ Vl_,
    float* __restrict__ O)
{
    extern __shared__ char smem[];
    const uint32_t sb = smem_u32(smem);
    const int t = threadIdx.x, lane = t & 31, w = t >> 5;
    const int qt = 15 - (int)blockIdx.x;    // big tiles first
    const int h = blockIdx.y;
    const int mw = w * 16;
    const size_t hoff = (size_t)h * S * HD;
    const __nv_bfloat16* Qhp = Qh_ + hoff + (size_t)qt * 128 * HD;
    const __nv_bfloat16* Qlp = Ql_ + hoff + (size_t)qt * 128 * HD;
    const __nv_bfloat16* Khp = Kh_ + hoff;
    const __nv_bfloat16* Klp = Kl_ + hoff;
    const __nv_bfloat16* Vhp = Vh_ + hoff;
    const __nv_bfloat16* Vlp = Vl_ + hoff;

    const uint32_t qB  = sb;                 // Qhi; Qlo at +QMAT
    const uint32_t kvB = sb + 2 * QMAT;      // stages: {Khi,Klo,Vhi,Vlo} x2

    // ---- Q tile load (once) ----
#pragma unroll
    for (int r = 0; r < 8; r++) {
        int idx = t + 256 * r;
        int row = idx >> 4, c = idx & 15;
        CPASYNC16(qB + row * FPB + c * 16,        Qhp + row * 128 + c * 8);
        CPASYNC16(qB + QMAT + row * FPB + c * 16, Qlp + row * 128 + c * 8);
    }
    CP_COMMIT();

#define LOADKV(kt_, p_) do {                                                  \
        uint32_t b_ = kvB + (p_) * (4 * KVMAT);                               \
        const __nv_bfloat16* g0 = Khp + (size_t)(kt_) * 64 * 128;             \
        const __nv_bfloat16* g1 = Klp + (size_t)(kt_) * 64 * 128;             \
        const __nv_bfloat16* g2 = Vhp + (size_t)(kt_) * 64 * 128;             \
        const __nv_bfloat16* g3 = Vlp + (size_t)(kt_) * 64 * 128;             \
        _Pragma("unroll")                                                     \
        for (int r_ = 0; r_ < 4; r_++) {                                      \
            int idx_ = t + 256 * r_;                                          \
            int row_ = idx_ >> 4, c_ = idx_ & 15;                             \
            uint32_t so_ = row_ * FPB + c_ * 16;                              \
            uint32_t go_ = row_ * 128 + c_ * 8;                               \
            CPASYNC16(b_ + so_,             g0 + go_);                        \
            CPASYNC16(b_ + KVMAT + so_,     g1 + go_);                        \
            CPASYNC16(b_ + 2 * KVMAT + so_, g2 + go_);                        \
            CPASYNC16(b_ + 3 * KVMAT + so_, g3 + go_);                        \
        }                                                                     \
        CP_COMMIT();                                                          \
    } while (0)

    float acc[16][4];
#pragma unroll
    for (int i = 0; i < 16; i++)
#pragma unroll
        for (int j = 0; j < 4; j++) acc[i][j] = 0.f;
    float m0 = -1e30f, m1 = -1e30f, l0 = 0.f, l1 = 0.f;

    const int ktmax = 2 * qt + 1;
    LOADKV(0, 0);

    for (int kt = 0; kt <= ktmax; kt++) {
        if (kt < ktmax) { LOADKV(kt + 1, (kt + 1) & 1); CP_WAIT(1); }
        else            { CP_WAIT(0); }
        __syncthreads();
        const uint32_t base = kvB + (kt & 1) * (4 * KVMAT);

        // ---- S = Qs @ K^T (3-term split) ----
        float s[8][4];
#pragma unroll
        for (int i = 0; i < 8; i++)
#pragma unroll
            for (int j = 0; j < 4; j++) s[i][j] = 0.f;
#pragma unroll
        for (int kc = 0; kc < 8; kc++) {
            uint32_t aH[4], aL[4];
            uint32_t aaddr = qB + (mw + (lane & 15)) * FPB + (2 * kc + (lane >> 4)) * 16;
            ldsm4(aH, aaddr);
            ldsm4(aL, aaddr + QMAT);
            uint32_t bH[8][2], bL[8][2];
#pragma unroll
            for (int j = 0; j < 4; j++) {
                int row = j * 16 + ((lane >> 4) << 3) + (lane & 7);
                uint32_t baddr = base + row * FPB + (2 * kc + ((lane >> 3) & 1)) * 16;
                uint32_t rh[4], rl[4];
                ldsm4(rh, baddr);
                ldsm4(rl, baddr + KVMAT);
                bH[2 * j][0] = rh[0]; bH[2 * j][1] = rh[1];
                bH[2 * j + 1][0] = rh[2]; bH[2 * j + 1][1] = rh[3];
                bL[2 * j][0] = rl[0]; bL[2 * j][1] = rl[1];
                bL[2 * j + 1][0] = rl[2]; bL[2 * j + 1][1] = rl[3];
            }
#pragma unroll
            for (int nb = 0; nb < 8; nb++) {
                mma16816(s[nb], aH, bH[nb]);
                mma16816(s[nb], aH, bL[nb]);
                mma16816(s[nb], aL, bH[nb]);
            }
        }

        // ---- causal mask ----
        const int qrow = qt * 128 + mw + (lane >> 2);
        if (kt * 64 + 63 > qt * 128 + mw) {
#pragma unroll
            for (int nb = 0; nb < 8; nb++) {
                int col = kt * 64 + 8 * nb + 2 * (lane & 3);
                if (col     > qrow)     s[nb][0] = -1e30f;
                if (col + 1 > qrow)     s[nb][1] = -1e30f;
                if (col     > qrow + 8) s[nb][2] = -1e30f;
                if (col + 1 > qrow + 8) s[nb][3] = -1e30f;
            }
        }

        // ---- online softmax (register-resident, rows r and r+8) ----
        float mx0 = -1e30f, mx1 = -1e30f;
#pragma unroll
        for (int nb = 0; nb < 8; nb++) {
            mx0 = fmaxf(mx0, fmaxf(s[nb][0], s[nb][1]));
            mx1 = fmaxf(mx1, fmaxf(s[nb][2], s[nb][3]));
        }
        mx0 = fmaxf(mx0, __shfl_xor_sync(0xffffffffu, mx0, 1));
        mx0 = fmaxf(mx0, __shfl_xor_sync(0xffffffffu, mx0, 2));
        mx1 = fmaxf(mx1, __shfl_xor_sync(0xffffffffu, mx1, 1));
        mx1 = fmaxf(mx1, __shfl_xor_sync(0xffffffffu, mx1, 2));
        float mn0 = fmaxf(m0, mx0), mn1 = fmaxf(m1, mx1);
        float al0 = __expf(m0 - mn0), al1 = __expf(m1 - mn1);
        m0 = mn0; m1 = mn1;

        float sum0 = 0.f, sum1 = 0.f;
        uint32_t ph0[8], ph1[8], pl0[8], pl1[8];
#pragma unroll
        for (int nb = 0; nb < 8; nb++) {
            float p0 = __expf(s[nb][0] - mn0), p1 = __expf(s[nb][1] - mn0);
            float p2 = __expf(s[nb][2] - mn1), p3 = __expf(s[nb][3] - mn1);
            sum0 += p0 + p1; sum1 += p2 + p3;
            __nv_bfloat162 h01 = __floats2bfloat162_rn(p0, p1);
            __nv_bfloat162 h23 = __floats2bfloat162_rn(p2, p3);
            ph0[nb] = *(uint32_t*)&h01;
            ph1[nb] = *(uint32_t*)&h23;
            pl0[nb] = pk2(p0 - __bfloat162float(h01.x), p1 - __bfloat162float(h01.y));
            pl1[nb] = pk2(p2 - __bfloat162float(h23.x), p3 - __bfloat162float(h23.y));
        }
        sum0 += __shfl_xor_sync(0xffffffffu, sum0, 1);
        sum0 += __shfl_xor_sync(0xffffffffu, sum0, 2);
        sum1 += __shfl_xor_sync(0xffffffffu, sum1, 1);
        sum1 += __shfl_xor_sync(0xffffffffu, sum1, 2);
        l0 = l0 * al0 + sum0;
        l1 = l1 * al1 + sum1;
#pragma unroll
        for (int nb = 0; nb < 16; nb++) {
            acc[nb][0] *= al0; acc[nb][1] *= al0;
            acc[nb][2] *= al1; acc[nb][3] *= al1;
        }

        // ---- O += P @ V (3-term split; V via ldmatrix.trans) ----
#pragma unroll
        for (int kc = 0; kc < 4; kc++) {
            uint32_t paH[4] = {ph0[2 * kc], ph1[2 * kc], ph0[2 * kc + 1], ph1[2 * kc + 1]};
            uint32_t paL[4] = {pl0[2 * kc], pl1[2 * kc], pl0[2 * kc + 1], pl1[2 * kc + 1]};
#pragma unroll
            for (int nb2 = 0; nb2 < 8; nb2++) {
                uint32_t vaddr = base + 2 * KVMAT +
                                 (kc * 16 + (lane & 15)) * FPB + (2 * nb2 + (lane >> 4)) * 16;
                uint32_t vh[4], vl[4];
                ldsm4t(vh, vaddr);
                ldsm4t(vl, vaddr + KVMAT);
                uint32_t bh0[2] = {vh[0], vh[1]}, bh1[2] = {vh[2], vh[3]};
                uint32_t bl0[2] = {vl[0], vl[1]}, bl1[2] = {vl[2], vl[3]};
                mma16816(acc[2 * nb2], paH, bh0);
                mma16816(acc[2 * nb2], paH, bl0);
                mma16816(acc[2 * nb2], paL, bh0);
                mma16816(acc[2 * nb2 + 1], paH, bh1);
                mma16816(acc[2 * nb2 + 1], paH, bl1);
                mma16816(acc[2 * nb2 + 1], paL, bh1);
            }
        }
        __syncthreads();
    }

    // ---- epilogue: normalize, write O[s][h*128+d] ----
    float inv0 = 1.f / l0, inv1 = 1.f / l1;
    int r = qt * 128 + mw + (lane >> 2);
#pragma unroll
    for (int nb = 0; nb < 16; nb++) {
        int col = h * 128 + 8 * nb + 2 * (lane & 3);
        *(float2*)&O[(size_t)r * D + col] =
            make_float2(acc[nb][0] * inv0, acc[nb][1] * inv0);
        *(float2*)&O[(size_t)(r + 8) * D + col] =
            make_float2(acc[nb][2] * inv1, acc[nb][3] * inv1);
    }
}

// ============================================================
extern "C" void kernel_launch(void* const* d_in, const int* in_sizes, int n_in,
                              void* d_out, int out_size)
{
    const float* hs   = (const float*)d_in[0];
    const float* cosT = (const float*)d_in[2];
    const float* sinT = (const float*)d_in[3];
    const float* Wq   = (const float*)d_in[4];
    const float* Wk   = (const float*)d_in[5];
    const float* Wv   = (const float*)d_in[6];
    const float* Wo   = (const float*)d_in[7];
    const float* lk   = (const float*)d_in[8];
    const float* lv   = (const float*)d_in[9];
    float* out = (float*)d_out;
    (void)in_sizes; (void)n_in; (void)out_size;

    float *q, *k, *v, *o;
    cudaGetSymbolAddress((void**)&q, g_q);
    cudaGetSymbolAddress((void**)&k, g_k);
    cudaGetSymbolAddress((void**)&v, g_v);
    cudaGetSymbolAddress((void**)&o, g_o);
    __nv_bfloat16 *hsH, *hsL, *wH, *wL, *oH, *oL;
    __nv_bfloat16 *qh, *ql, *kh, *kl, *vh, *vl;
    cudaGetSymbolAddress((void**)&hsH, g_hs_hi);
    cudaGetSymbolAddress((void**)&hsL, g_hs_lo);
    cudaGetSymbolAddress((void**)&wH, g_w_hi);
    cudaGetSymbolAddress((void**)&wL, g_w_lo);
    cudaGetSymbolAddress((void**)&oH, g_o_hi);
    cudaGetSymbolAddress((void**)&oL, g_o_lo);
    cudaGetSymbolAddress((void**)&qh, g_qh);
    cudaGetSymbolAddress((void**)&ql, g_ql);
    cudaGetSymbolAddress((void**)&kh, g_kh);
    cudaGetSymbolAddress((void**)&kl, g_kl);
    cudaGetSymbolAddress((void**)&vh, g_vh);
    cudaGetSymbolAddress((void**)&vl, g_vl);

    const int n = S * D;
    const int sg = n / 4 / 256;
    split_kernel<<<sg, 256>>>(hs, hsH, hsL, n);
    split_kernel<<<sg, 256>>>(Wq, wH + 0 * (size_t)n, wL + 0 * (size_t)n, n);
    split_kernel<<<sg, 256>>>(Wk, wH + 1 * (size_t)n, wL + 1 * (size_t)n, n);
    split_kernel<<<sg, 256>>>(Wv, wH + 2 * (size_t)n, wL + 2 * (size_t)n, n);
    split_kernel<<<sg, 256>>>(Wo, wH + 3 * (size_t)n, wL + 3 * (size_t)n, n);

    cudaFuncSetAttribute(gemm_mma_kernel,
                         cudaFuncAttributeMaxDynamicSharedMemorySize, GSMEM);
    dim3 gg(D / 128, S / 128);
    gemm_mma_kernel<<<gg, 256, GSMEM>>>(hsH, hsL, wH + 0 * (size_t)n, wL + 0 * (size_t)n, q, 1);
    gemm_mma_kernel<<<gg, 256, GSMEM>>>(hsH, hsL, wH + 1 * (size_t)n, wL + 1 * (size_t)n, k, 1);
    gemm_mma_kernel<<<gg, 256, GSMEM>>>(hsH, hsL, wH + 2 * (size_t)n, wL + 2 * (size_t)n, v, 1);

    rope_split_kernel<<<dim3(S, H), 128>>>(q, k, v, cosT, sinT, lk, lv,
                                           qh, ql, kh, kl, vh, vl);

    int fsmem = 2 * QMAT + 2 * 4 * KVMAT;   // 208896
    cudaFuncSetAttribute(flash_mma_kernel,
                         cudaFuncAttributeMaxDynamicSharedMemorySize, fsmem);
    flash_mma_kernel<<<dim3(16, 16), 256, fsmem>>>(qh, ql, kh, kl, vh, vl, o);

    split_kernel<<<sg, 256>>>(o, oH, oL, n);
    gemm_mma_kernel<<<gg, 256, GSMEM>>>(oH, oL, wH + 3 * (size_t)n, wL + 3 * (size_t)n, out, 0);
}

// round 6
// speedup vs baseline: 3.0621x; 1.1140x over previous
#include <cuda_runtime.h>
#include <cuda_bf16.h>
#include <cstdint>
#include <math.h>

#define S 2048
#define D 2048
#define H 16
#define HD 128

// ---- scratch (allocation-free rule: __device__ globals) ----
__device__ float g_q[H * S * HD];
__device__ float g_k[H * S * HD];
__device__ float g_v[H * S * HD];
__device__ __nv_bfloat16 g_hs_hi[S * D], g_hs_lo[S * D];
__device__ __nv_bfloat16 g_w_hi[4][D * D], g_w_lo[4][D * D];
__device__ __nv_bfloat16 g_o_hi[S * D], g_o_lo[S * D];
__device__ __nv_bfloat16 g_qh[H * S * HD], g_ql[H * S * HD];
__device__ __nv_bfloat16 g_kh[H * S * HD], g_kl[H * S * HD];
__device__ __nv_bfloat16 g_vh[H * S * HD], g_vl[H * S * HD];

// ============================================================
// helpers (arch-agnostic: mma.sync / ldmatrix / cp.async)
// ============================================================
__device__ __forceinline__ uint32_t smem_u32(const void* p) {
    uint32_t a;
    asm("{ .reg .u64 t; cvta.to.shared.u64 t, %1; cvt.u32.u64 %0, t; }"
        : "=r"(a) : "l"(p));
    return a;
}
__device__ __forceinline__ void mma16816(float* c, const uint32_t* a,
                                         const uint32_t* b) {
    asm volatile(
        "mma.sync.aligned.m16n8k16.row.col.f32.bf16.bf16.f32 "
        "{%0,%1,%2,%3}, {%4,%5,%6,%7}, {%8,%9}, {%0,%1,%2,%3};"
        : "+f"(c[0]), "+f"(c[1]), "+f"(c[2]), "+f"(c[3])
        : "r"(a[0]), "r"(a[1]), "r"(a[2]), "r"(a[3]), "r"(b[0]), "r"(b[1]));
}
__device__ __forceinline__ void ldsm4(uint32_t* r, uint32_t addr) {
    asm volatile("ldmatrix.sync.aligned.m8n8.x4.shared.b16 {%0,%1,%2,%3}, [%4];"
                 : "=r"(r[0]), "=r"(r[1]), "=r"(r[2]), "=r"(r[3]) : "r"(addr));
}
__device__ __forceinline__ void ldsm4t(uint32_t* r, uint32_t addr) {
    asm volatile("ldmatrix.sync.aligned.m8n8.x4.trans.shared.b16 {%0,%1,%2,%3}, [%4];"
                 : "=r"(r[0]), "=r"(r[1]), "=r"(r[2]), "=r"(r[3]) : "r"(addr));
}
#define CPASYNC16(sa, ga) \
    asm volatile("cp.async.cg.shared.global [%0], [%1], 16;" \
                 :: "r"(sa), "l"(ga) : "memory")
#define CP_COMMIT() asm volatile("cp.async.commit_group;" ::: "memory")
#define CP_WAIT(N)  asm volatile("cp.async.wait_group %0;" :: "n"(N) : "memory")

__device__ __forceinline__ uint32_t pk2(float a, float b) {
    __nv_bfloat162 t = __floats2bfloat162_rn(a, b);
    return *(uint32_t*)&t;
}

// ============================================================
// fp32 -> (hi, lo) bf16 split
// ============================================================
__global__ __launch_bounds__(256) void split_kernel(
    const float* __restrict__ x, __nv_bfloat16* __restrict__ hi,
    __nv_bfloat16* __restrict__ lo, int n)
{
    int i = (blockIdx.x * 256 + threadIdx.x) * 4;
    if (i >= n) return;
    float4 v = *(const float4*)(x + i);
    float f[4] = {v.x, v.y, v.z, v.w};
    __nv_bfloat16 hb[4], lb[4];
#pragma unroll
    for (int j = 0; j < 4; j++) {
        hb[j] = __float2bfloat16(f[j]);
        lb[j] = __float2bfloat16(f[j] - __bfloat162float(hb[j]));
    }
    ((__nv_bfloat162*)(hi + i))[0] = __nv_bfloat162(hb[0], hb[1]);
    ((__nv_bfloat162*)(hi + i))[1] = __nv_bfloat162(hb[2], hb[3]);
    ((__nv_bfloat162*)(lo + i))[0] = __nv_bfloat162(lb[0], lb[1]);
    ((__nv_bfloat162*)(lo + i))[1] = __nv_bfloat162(lb[2], lb[3]);
}

// ============================================================
// mma.sync split-bf16 GEMM: C = A @ B^T, M=N=K=2048.
// CTA tile 128x128, K-stage 64, double-buffered, pitch 144B.
// Term-outermost mma order (breaks accumulator RAW chains).
// headmode=1: C[((n>>7)*2048 + m)*128 + (n&127)], else C[m*2048+n].
// ============================================================
#define PITCH 144
#define MATSZ (128 * PITCH)      // 18432
#define STAGESZ (4 * MATSZ)      // 73728
#define GSMEM (2 * STAGESZ)      // 147456

__global__ __launch_bounds__(256, 1) void gemm_mma_kernel(
    const __nv_bfloat16* __restrict__ Ahi, const __nv_bfloat16* __restrict__ Alo,
    const __nv_bfloat16* __restrict__ Bhi, const __nv_bfloat16* __restrict__ Blo,
    float* __restrict__ C, int headmode)
{
    extern __shared__ char smem[];
    const uint32_t sb = smem_u32(smem);
    const int t = threadIdx.x;
    const int lane = t & 31;
    const int w = t >> 5;
    const int mw = (w >> 1) * 32;
    const int nw = (w & 1) * 64;
    const int mbase = blockIdx.y * 128;
    const int nbase = blockIdx.x * 128;

    const __nv_bfloat16* mats[4] = {
        Ahi + (size_t)mbase * 2048, Alo + (size_t)mbase * 2048,
        Bhi + (size_t)nbase * 2048, Blo + (size_t)nbase * 2048 };

    float acc[2][8][4];
#pragma unroll
    for (int i = 0; i < 2; i++)
#pragma unroll
        for (int j = 0; j < 8; j++)
#pragma unroll
            for (int k = 0; k < 4; k++) acc[i][j][k] = 0.f;

    // stage: 4 mats x 128 rows x 64 bf16 (128B data, 144B pitch)
#define LOAD_STAGE(sidx, k0) do {                                            \
        uint32_t base = sb + ((sidx) & 1) * STAGESZ;                         \
        _Pragma("unroll")                                                    \
        for (int mat = 0; mat < 4; mat++) {                                  \
            _Pragma("unroll")                                                \
            for (int r = 0; r < 4; r++) {                                    \
                int idx = t + 256 * r;                                       \
                int row = idx >> 3, c = idx & 7;                             \
                CPASYNC16(base + mat * MATSZ + row * PITCH + c * 16,         \
                          mats[mat] + (size_t)row * 2048 + (k0) + c * 8);    \
            }                                                                \
        }                                                                    \
        CP_COMMIT();                                                         \
    } while (0)

    LOAD_STAGE(0, 0);

    for (int s = 0; s < 32; s++) {
        if (s < 31) { LOAD_STAGE(s + 1, (s + 1) * 64); CP_WAIT(1); }
        else        { CP_WAIT(0); }
        __syncthreads();
        const uint32_t base = sb + (s & 1) * STAGESZ;
        const uint32_t aHiB = base;
        const uint32_t aLoB = base + MATSZ;
        const uint32_t bHiB = base + 2 * MATSZ;
        const uint32_t bLoB = base + 3 * MATSZ;
#pragma unroll
        for (int ks = 0; ks < 4; ks++) {
            uint32_t a_hi[2][4], a_lo[2][4], b_hi[8][2], b_lo[8][2];
#pragma unroll
            for (int mt = 0; mt < 2; mt++) {
                int row = mw + mt * 16 + (lane & 15);
                int chunk = 2 * ks + (lane >> 4);
                uint32_t off = row * PITCH + chunk * 16;
                ldsm4(a_hi[mt], aHiB + off);
                ldsm4(a_lo[mt], aLoB + off);
            }
#pragma unroll
            for (int j = 0; j < 4; j++) {
                int row = nw + j * 16 + ((lane >> 4) << 3) + (lane & 7);
                int chunk = 2 * ks + ((lane >> 3) & 1);
                uint32_t off = row * PITCH + chunk * 16;
                uint32_t rh[4], rl[4];
                ldsm4(rh, bHiB + off);
                ldsm4(rl, bLoB + off);
                b_hi[2 * j][0] = rh[0]; b_hi[2 * j][1] = rh[1];
                b_hi[2 * j + 1][0] = rh[2]; b_hi[2 * j + 1][1] = rh[3];
                b_lo[2 * j][0] = rl[0]; b_lo[2 * j][1] = rl[1];
                b_lo[2 * j + 1][0] = rl[2]; b_lo[2 * j + 1][1] = rl[3];
            }
            // term-outermost: 16 independent accs between reuses
#pragma unroll
            for (int mt = 0; mt < 2; mt++)
#pragma unroll
                for (int nt = 0; nt < 8; nt++)
                    mma16816(acc[mt][nt], a_hi[mt], b_hi[nt]);
#pragma unroll
            for (int mt = 0; mt < 2; mt++)
#pragma unroll
                for (int nt = 0; nt < 8; nt++)
                    mma16816(acc[mt][nt], a_hi[mt], b_lo[nt]);
#pragma unroll
            for (int mt = 0; mt < 2; mt++)
#pragma unroll
                for (int nt = 0; nt < 8; nt++)
                    mma16816(acc[mt][nt], a_lo[mt], b_hi[nt]);
        }
        __syncthreads();
    }

#pragma unroll
    for (int mt = 0; mt < 2; mt++)
#pragma unroll
        for (int nt = 0; nt < 8; nt++) {
            const float* a = acc[mt][nt];
            int r0 = mbase + mw + mt * 16 + (lane >> 2);
            int n  = nbase + nw + nt * 8 + 2 * (lane & 3);
            if (headmode) {
                float* p0 = C + ((size_t)(n >> 7) * 2048 + r0) * 128 + (n & 127);
                float* p1 = C + ((size_t)(n >> 7) * 2048 + r0 + 8) * 128 + (n & 127);
                *(float2*)p0 = make_float2(a[0], a[1]);
                *(float2*)p1 = make_float2(a[2], a[3]);
            } else {
                *(float2*)(C + (size_t)r0 * 2048 + n)       = make_float2(a[0], a[1]);
                *(float2*)(C + (size_t)(r0 + 8) * 2048 + n) = make_float2(a[2], a[3]);
            }
        }
}

// ============================================================
// RoPE + IA3 + scale, emitting split bf16 q,k,v.
// ============================================================
__global__ __launch_bounds__(128) void rope_split_kernel(
    const float* __restrict__ Qm, const float* __restrict__ Km,
    const float* __restrict__ Vm,
    const float* __restrict__ cosT, const float* __restrict__ sinT,
    const float* __restrict__ lk, const float* __restrict__ lv,
    __nv_bfloat16* __restrict__ qh, __nv_bfloat16* __restrict__ ql,
    __nv_bfloat16* __restrict__ kh, __nv_bfloat16* __restrict__ kl,
    __nv_bfloat16* __restrict__ vh, __nv_bfloat16* __restrict__ vl)
{
    const int s = blockIdx.x;
    const int h = blockIdx.y;
    const int d = threadIdx.x;
    const float scale = 0.08838834764831845f;   // 1/sqrt(128)
    size_t rb = ((size_t)h * S + s) * HD;
    float c  = cosT[s * HD + d];
    float sn = sinT[s * HD + d];
    int   p  = d ^ 64;
    float sign = (d < 64) ? -1.f : 1.f;
    float q = (Qm[rb + d] * c + sign * Qm[rb + p] * sn) * lk[h * HD + d] * scale;
    float k = Km[rb + d] * c + sign * Km[rb + p] * sn;
    float v = Vm[rb + d] * lv[h * HD + d];
    __nv_bfloat16 qH = __float2bfloat16(q);
    __nv_bfloat16 kH = __float2bfloat16(k);
    __nv_bfloat16 vH = __float2bfloat16(v);
    qh[rb + d] = qH; ql[rb + d] = __float2bfloat16(q - __bfloat162float(qH));
    kh[rb + d] = kH; kl[rb + d] = __float2bfloat16(k - __bfloat162float(kH));
    vh[rb + d] = vH; vl[rb + d] = __float2bfloat16(v - __bfloat162float(vH));
}

// ============================================================
// Causal flash attention, mma.sync split-bf16.
// BQ=128, BK=64, 8 warps, double-buffered K/V.
// Epilogue emits split bf16 O (fused with o-split).
// ============================================================
#define FPB 272
#define QMAT (128 * FPB)
#define KVMAT (64 * FPB)

__global__ __launch_bounds__(256, 1) void flash_mma_kernel(
    const __nv_bfloat16* __restrict__ Qh_, const __nv_bfloat16* __restrict__ Ql_,
    const __nv_bfloat16* __restrict__ Kh_, const __nv_bfloat16* __restrict__ Kl_,
    const __nv_bfloat16* __restrict__ Vh_, const __nv_bfloat16* __restrict__ Vl_,
    __nv_bfloat16* __restrict__ OH, __nv_bfloat16* __restrict__ OL)
{
    extern __shared__ char smem[];
    const uint32_t sb = smem_u32(smem);
    const int t = threadIdx.x, lane = t & 31, w = t >> 5;
    const int qt = 15 - (int)blockIdx.x;
    const int h = blockIdx.y;
    const int mw = w * 16;
    const size_t hoff = (size_t)h * S * HD;
    const __nv_bfloat16* Qhp = Qh_ + hoff + (size_t)qt * 128 * HD;
    const __nv_bfloat16* Qlp = Ql_ + hoff + (size_t)qt * 128 * HD;
    const __nv_bfloat16* Khp = Kh_ + hoff;
    const __nv_bfloat16* Klp = Kl_ + hoff;
    const __nv_bfloat16* Vhp = Vh_ + hoff;
    const __nv_bfloat16* Vlp = Vl_ + hoff;

    const uint32_t qB  = sb;
    const uint32_t kvB = sb + 2 * QMAT;

#pragma unroll
    for (int r = 0; r < 8; r++) {
        int idx = t + 256 * r;
        int row = idx >> 4, c = idx & 15;
        CPASYNC16(qB + row * FPB + c * 16,        Qhp + row * 128 + c * 8);
        CPASYNC16(qB + QMAT + row * FPB + c * 16, Qlp + row * 128 + c * 8);
    }
    CP_COMMIT();

#define LOADKV(kt_, p_) do {                                                  \
        uint32_t b_ = kvB + (p_) * (4 * KVMAT);                               \
        const __nv_bfloat16* g0 = Khp + (size_t)(kt_) * 64 * 128;             \
        const __nv_bfloat16* g1 = Klp + (size_t)(kt_) * 64 * 128;             \
        const __nv_bfloat16* g2 = Vhp + (size_t)(kt_) * 64 * 128;             \
        const __nv_bfloat16* g3 = Vlp + (size_t)(kt_) * 64 * 128;             \
        _Pragma("unroll")                                                     \
        for (int r_ = 0; r_ < 4; r_++) {                                      \
            int idx_ = t + 256 * r_;                                          \
            int row_ = idx_ >> 4, c_ = idx_ & 15;                             \
            uint32_t so_ = row_ * FPB + c_ * 16;                              \
            uint32_t go_ = row_ * 128 + c_ * 8;                               \
            CPASYNC16(b_ + so_,             g0 + go_);                        \
            CPASYNC16(b_ + KVMAT + so_,     g1 + go_);                        \
            CPASYNC16(b_ + 2 * KVMAT + so_, g2 + go_);                        \
            CPASYNC16(b_ + 3 * KVMAT + so_, g3 + go_);                        \
        }                                                                     \
        CP_COMMIT();                                                          \
    } while (0)

    float acc[16][4];
#pragma unroll
    for (int i = 0; i < 16; i++)
#pragma unroll
        for (int j = 0; j < 4; j++) acc[i][j] = 0.f;
    float m0 = -1e30f, m1 = -1e30f, l0 = 0.f, l1 = 0.f;

    const int ktmax = 2 * qt + 1;
    LOADKV(0, 0);

    for (int kt = 0; kt <= ktmax; kt++) {
        if (kt < ktmax) { LOADKV(kt + 1, (kt + 1) & 1); CP_WAIT(1); }
        else            { CP_WAIT(0); }
        __syncthreads();
        const uint32_t base = kvB + (kt & 1) * (4 * KVMAT);

        float s[8][4];
#pragma unroll
        for (int i = 0; i < 8; i++)
#pragma unroll
            for (int j = 0; j < 4; j++) s[i][j] = 0.f;
#pragma unroll
        for (int kc = 0; kc < 8; kc++) {
            uint32_t aH[4], aL[4];
            uint32_t aaddr = qB + (mw + (lane & 15)) * FPB + (2 * kc + (lane >> 4)) * 16;
            ldsm4(aH, aaddr);
            ldsm4(aL, aaddr + QMAT);
            uint32_t bH[8][2], bL[8][2];
#pragma unroll
            for (int j = 0; j < 4; j++) {
                int row = j * 16 + ((lane >> 4) << 3) + (lane & 7);
                uint32_t baddr = base + row * FPB + (2 * kc + ((lane >> 3) & 1)) * 16;
                uint32_t rh[4], rl[4];
                ldsm4(rh, baddr);
                ldsm4(rl, baddr + KVMAT);
                bH[2 * j][0] = rh[0]; bH[2 * j][1] = rh[1];
                bH[2 * j + 1][0] = rh[2]; bH[2 * j + 1][1] = rh[3];
                bL[2 * j][0] = rl[0]; bL[2 * j][1] = rl[1];
                bL[2 * j + 1][0] = rl[2]; bL[2 * j + 1][1] = rl[3];
            }
#pragma unroll
            for (int nb = 0; nb < 8; nb++)
                mma16816(s[nb], aH, bH[nb]);
#pragma unroll
            for (int nb = 0; nb < 8; nb++)
                mma16816(s[nb], aH, bL[nb]);
#pragma unroll
            for (int nb = 0; nb < 8; nb++)
                mma16816(s[nb], aL, bH[nb]);
        }

        const int qrow = qt * 128 + mw + (lane >> 2);
        if (kt * 64 + 63 > qt * 128 + mw) {
#pragma unroll
            for (int nb = 0; nb < 8; nb++) {
                int col = kt * 64 + 8 * nb + 2 * (lane & 3);
                if (col     > qrow)     s[nb][0] = -1e30f;
                if (col + 1 > qrow)     s[nb][1] = -1e30f;
                if (col     > qrow + 8) s[nb][2] = -1e30f;
                if (col + 1 > qrow + 8) s[nb][3] = -1e30f;
            }
        }

        float mx0 = -1e30f, mx1 = -1e30f;
#pragma unroll
        for (int nb = 0; nb < 8; nb++) {
            mx0 = fmaxf(mx0, fmaxf(s[nb][0], s[nb][1]));
            mx1 = fmaxf(mx1, fmaxf(s[nb][2], s[nb][3]));
        }
        mx0 = fmaxf(mx0, __shfl_xor_sync(0xffffffffu, mx0, 1));
        mx0 = fmaxf(mx0, __shfl_xor_sync(0xffffffffu, mx0, 2));
        mx1 = fmaxf(mx1, __shfl_xor_sync(0xffffffffu, mx1, 1));
        mx1 = fmaxf(mx1, __shfl_xor_sync(0xffffffffu, mx1, 2));
        float mn0 = fmaxf(m0, mx0), mn1 = fmaxf(m1, mx1);
        float al0 = __expf(m0 - mn0), al1 = __expf(m1 - mn1);
        m0 = mn0; m1 = mn1;

        float sum0 = 0.f, sum1 = 0.f;
        uint32_t ph0[8], ph1[8], pl0[8], pl1[8];
#pragma unroll
        for (int nb = 0; nb < 8; nb++) {
            float p0 = __expf(s[nb][0] - mn0), p1 = __expf(s[nb][1] - mn0);
            float p2 = __expf(s[nb][2] - mn1), p3 = __expf(s[nb][3] - mn1);
            sum0 += p0 + p1; sum1 += p2 + p3;
            __nv_bfloat162 h01 = __floats2bfloat162_rn(p0, p1);
            __nv_bfloat162 h23 = __floats2bfloat162_rn(p2, p3);
            ph0[nb] = *(uint32_t*)&h01;
            ph1[nb] = *(uint32_t*)&h23;
            pl0[nb] = pk2(p0 - __bfloat162float(h01.x), p1 - __bfloat162float(h01.y));
            pl1[nb] = pk2(p2 - __bfloat162float(h23.x), p3 - __bfloat162float(h23.y));
        }
        sum0 += __shfl_xor_sync(0xffffffffu, sum0, 1);
        sum0 += __shfl_xor_sync(0xffffffffu, sum0, 2);
        sum1 += __shfl_xor_sync(0xffffffffu, sum1, 1);
        sum1 += __shfl_xor_sync(0xffffffffu, sum1, 2);
        l0 = l0 * al0 + sum0;
        l1 = l1 * al1 + sum1;
#pragma unroll
        for (int nb = 0; nb < 16; nb++) {
            acc[nb][0] *= al0; acc[nb][1] *= al0;
            acc[nb][2] *= al1; acc[nb][3] *= al1;
        }

#pragma unroll
        for (int kc = 0; kc < 4; kc++) {
            uint32_t paH[4] = {ph0[2 * kc], ph1[2 * kc], ph0[2 * kc + 1], ph1[2 * kc + 1]};
            uint32_t paL[4] = {pl0[2 * kc], pl1[2 * kc], pl0[2 * kc + 1], pl1[2 * kc + 1]};
#pragma unroll
            for (int nb2 = 0; nb2 < 8; nb2++) {
                uint32_t vaddr = base + 2 * KVMAT +
                                 (kc * 16 + (lane & 15)) * FPB + (2 * nb2 + (lane >> 4)) * 16;
                uint32_t vh[4], vl[4];
                ldsm4t(vh, vaddr);
                ldsm4t(vl, vaddr + KVMAT);
                uint32_t bh0[2] = {vh[0], vh[1]}, bh1[2] = {vh[2], vh[3]};
                uint32_t bl0[2] = {vl[0], vl[1]}, bl1[2] = {vl[2], vl[3]};
                mma16816(acc[2 * nb2], paH, bh0);
                mma16816(acc[2 * nb2 + 1], paH, bh1);
                mma16816(acc[2 * nb2], paH, bl0);
                mma16816(acc[2 * nb2 + 1], paH, bl1);
                mma16816(acc[2 * nb2], paL, bh0);
                mma16816(acc[2 * nb2 + 1], paL, bh1);
            }
        }
        __syncthreads();
    }

    // ---- epilogue: normalize, split to hi/lo bf16, write ----
    float inv0 = 1.f / l0, inv1 = 1.f / l1;
    int r = qt * 128 + mw + (lane >> 2);
#pragma unroll
    for (int nb = 0; nb < 16; nb++) {
        int col = h * 128 + 8 * nb + 2 * (lane & 3);
        float v0 = acc[nb][0] * inv0, v1 = acc[nb][1] * inv0;
        float v2 = acc[nb][2] * inv1, v3 = acc[nb][3] * inv1;
        __nv_bfloat162 h01 = __floats2bfloat162_rn(v0, v1);
        __nv_bfloat162 h23 = __floats2bfloat162_rn(v2, v3);
        __nv_bfloat162 l01 = __floats2bfloat162_rn(
            v0 - __bfloat162float(h01.x), v1 - __bfloat162float(h01.y));
        __nv_bfloat162 l23 = __floats2bfloat162_rn(
            v2 - __bfloat162float(h23.x), v3 - __bfloat162float(h23.y));
        *(__nv_bfloat162*)&OH[(size_t)r * D + col]       = h01;
        *(__nv_bfloat162*)&OL[(size_t)r * D + col]       = l01;
        *(__nv_bfloat162*)&OH[(size_t)(r + 8) * D + col] = h23;
        *(__nv_bfloat162*)&OL[(size_t)(r + 8) * D + col] = l23;
    }
}

// ============================================================
extern "C" void kernel_launch(void* const* d_in, const int* in_sizes, int n_in,
                              void* d_out, int out_size)
{
    const float* hs   = (const float*)d_in[0];
    const float* cosT = (const float*)d_in[2];
    const float* sinT = (const float*)d_in[3];
    const float* Wq   = (const float*)d_in[4];
    const float* Wk   = (const float*)d_in[5];
    const float* Wv   = (const float*)d_in[6];
    const float* Wo   = (const float*)d_in[7];
    const float* lk   = (const float*)d_in[8];
    const float* lv   = (const float*)d_in[9];
    float* out = (float*)d_out;
    (void)in_sizes; (void)n_in; (void)out_size;

    float *q, *k, *v;
    cudaGetSymbolAddress((void**)&q, g_q);
    cudaGetSymbolAddress((void**)&k, g_k);
    cudaGetSymbolAddress((void**)&v, g_v);
    __nv_bfloat16 *hsH, *hsL, *wH, *wL, *oH, *oL;
    __nv_bfloat16 *qh, *ql, *kh, *kl, *vh, *vl;
    cudaGetSymbolAddress((void**)&hsH, g_hs_hi);
    cudaGetSymbolAddress((void**)&hsL, g_hs_lo);
    cudaGetSymbolAddress((void**)&wH, g_w_hi);
    cudaGetSymbolAddress((void**)&wL, g_w_lo);
    cudaGetSymbolAddress((void**)&oH, g_o_hi);
    cudaGetSymbolAddress((void**)&oL, g_o_lo);
    cudaGetSymbolAddress((void**)&qh, g_qh);
    cudaGetSymbolAddress((void**)&ql, g_ql);
    cudaGetSymbolAddress((void**)&kh, g_kh);
    cudaGetSymbolAddress((void**)&kl, g_kl);
    cudaGetSymbolAddress((void**)&vh, g_vh);
    cudaGetSymbolAddress((void**)&vl, g_vl);

    const int n = S * D;
    const int sg = n / 4 / 256;
    split_kernel<<<sg, 256>>>(hs, hsH, hsL, n);
    split_kernel<<<sg, 256>>>(Wq, wH + 0 * (size_t)n, wL + 0 * (size_t)n, n);
    split_kernel<<<sg, 256>>>(Wk, wH + 1 * (size_t)n, wL + 1 * (size_t)n, n);
    split_kernel<<<sg, 256>>>(Wv, wH + 2 * (size_t)n, wL + 2 * (size_t)n, n);
    split_kernel<<<sg, 256>>>(Wo, wH + 3 * (size_t)n, wL + 3 * (size_t)n, n);

    cudaFuncSetAttribute(gemm_mma_kernel,
                         cudaFuncAttributeMaxDynamicSharedMemorySize, GSMEM);
    dim3 gg(D / 128, S / 128);
    gemm_mma_kernel<<<gg, 256, GSMEM>>>(hsH, hsL, wH + 0 * (size_t)n, wL + 0 * (size_t)n, q, 1);
    gemm_mma_kernel<<<gg, 256, GSMEM>>>(hsH, hsL, wH + 1 * (size_t)n, wL + 1 * (size_t)n, k, 1);
    gemm_mma_kernel<<<gg, 256, GSMEM>>>(hsH, hsL, wH + 2 * (size_t)n, wL + 2 * (size_t)n, v, 1);

    rope_split_kernel<<<dim3(S, H), 128>>>(q, k, v, cosT, sinT, lk, lv,
                                           qh, ql, kh, kl, vh, vl);

    int fsmem = 2 * QMAT + 2 * 4 * KVMAT;
    cudaFuncSetAttribute(flash_mma_kernel,
                         cudaFuncAttributeMaxDynamicSharedMemorySize, fsmem);
    flash_mma_kernel<<<dim3(16, 16), 256, fsmem>>>(qh, ql, kh, kl, vh, vl, oH, oL);

    gemm_mma_kernel<<<gg, 256, GSMEM>>>(oH, oL, wH + 3 * (size_t)n, wL + 3 * (size_t)n, out, 0);
}